// round 8
// baseline (speedup 1.0000x reference)
#include <cuda_runtime.h>

// ---------------------------------------------------------------------------
// MultiHeadAttention: out = softmax((X Wq^T)(X Wk^T)^T / sqrt(dk) + mask) (X Wv^T) Wo^T
// B=2, S=2048, D_MODEL=1024, H=16, DK=64
// Strategy: tf32 mma.sync with hi/lo (3xTF32) splits for dense GEMMs,
//           split-K 2xTF32 for QK^T, 1xTF32 for PV. fp32 softmax.
// R1: register-prefetch software pipeline in gemm_body.
// R2: double-buffered smem in gemm_body -> one __syncthreads per K-step.
// R3: register-prefetch of next K/V tile in attn_kernel.
// R5: double-buffered K/V smem in attn_kernel -> one __syncthreads per tile.
// R6: GEMM BK=16 (80 KB smem) + __launch_bounds__(256,2): 2 CTAs/SM.
// R7: GEMM MMA phase split into 3 fragment passes (al*bh, ah*bh, ah*bl)
//     to cut peak fragment registers 48 -> 24 so the 128-reg cap from
//     launch_bounds(256,2) does not spill.
// ---------------------------------------------------------------------------

constexpr int DMODEL = 1024;
constexpr int HEADS  = 16;
constexpr int DK     = 64;
constexpr int BATCH  = 2;
constexpr int SEQ    = 2048;
constexpr int NTOK   = BATCH * SEQ;   // 4096

// Scratch (head-split layout [B,H,S,DK])
__device__ float g_Qh[NTOK * DMODEL];
__device__ float g_Kh[NTOK * DMODEL];
__device__ float g_Vh[NTOK * DMODEL];
__device__ float g_Oh[NTOK * DMODEL];

__device__ __forceinline__ unsigned f2tf(float x) {
    unsigned r;
    asm("cvt.rna.tf32.f32 %0, %1;" : "=r"(r) : "f"(x));
    return r;
}

__device__ __forceinline__ void split_tf32(float x, float& hi, float& lo) {
    hi = __uint_as_float(f2tf(x));
    lo = __uint_as_float(f2tf(x - hi));
}

// D = A(16x8) * B(8x8) + D, tf32
__device__ __forceinline__ void mma8(float c[4], unsigned a0, unsigned a1,
                                     unsigned a2, unsigned a3,
                                     unsigned b0, unsigned b1) {
    asm("mma.sync.aligned.m16n8k8.row.col.f32.tf32.tf32.f32 "
        "{%0,%1,%2,%3},{%4,%5,%6,%7},{%8,%9},{%0,%1,%2,%3};"
        : "+f"(c[0]), "+f"(c[1]), "+f"(c[2]), "+f"(c[3])
        : "r"(a0), "r"(a1), "r"(a2), "r"(a3), "r"(b0), "r"(b1));
}

// ---------------------------------------------------------------------------
// Generic NT GEMM: C[M,N] = A[M,K] * Bw[N,K]^T with 3xTF32.
// AMODE 0: A plain row-major [M,K].  AMODE 1: A gathered from [B,H,S,DK].
// CMODE 0: C plain row-major [M,N].  CMODE 1: C scattered to [B,H,S,DK].
// Block: 256 threads, tile 128x128, BK=16. Warps 2x4, each 64x32.
// Double-buffered dynamic smem (80 KB) + register prefetch; 2 CTAs/SM.
// MMA phase: 3 low-pressure fragment passes per ks.
// ---------------------------------------------------------------------------
constexpr int GBM = 128, GBN = 128, GBK = 16, GLDA = 20;  // stride 20: conflict-free
constexpr int GSLOT = GBM * GLDA;            // one array (floats)
constexpr int GBUF  = 4 * GSLOT;             // Ash,Asl,Bsh,Bsl (floats)
constexpr size_t GEMM_SHM = (size_t)2 * GBUF * sizeof(float);  // 81920 B

template <int AMODE, int CMODE>
__device__ __forceinline__ void gemm_body(const float* __restrict__ A,
                                          const float* __restrict__ Bw,
                                          float* __restrict__ C) {
    constexpr int BM = GBM, BN = GBN, BK = GBK, LDA = GLDA;
    constexpr int K = DMODEL, N = DMODEL;

    extern __shared__ float smg[];

    const int tid  = threadIdx.x;
    const int lane = tid & 31;
    const int warp = tid >> 5;
    const int wm = (warp >> 2) * 64;  // warp row offset in tile
    const int wn = (warp & 3) * 32;   // warp col offset in tile
    const int bm = blockIdx.y * BM;
    const int bn = blockIdx.x * BN;
    const int r0 = lane >> 2;         // 0..7
    const int cq = lane & 3;          // 0..3

    float acc[4][4][4];
#pragma unroll
    for (int i = 0; i < 4; i++)
#pragma unroll
        for (int j = 0; j < 4; j++)
#pragma unroll
            for (int t = 0; t < 4; t++) acc[i][j][t] = 0.f;

    // --- global loader for one staging slot (it = 0,1) ---
    auto load_g = [&](int kt, int it, float4& av, float4& bv) {
        int f   = tid + it * 256;      // 0..511
        int row = f >> 2;              // 0..127
        int c4  = (f & 3) * 4;         // 0..12
        if (AMODE == 0) {
            av = *(const float4*)(A + (size_t)(bm + row) * K + kt + c4);
        } else {
            int ig = bm + row;
            int b_ = ig >> 11, s = ig & 2047;
            int k0 = kt + c4;
            int h = k0 >> 6, d = k0 & 63;
            av = *(const float4*)(A + ((size_t)((b_ * HEADS + h) * SEQ + s)) * DK + d);
        }
        bv = *(const float4*)(Bw + (size_t)(bn + row) * K + kt + c4);
    };

    // --- split prefetched regs and store into buffer p ---
    auto stage = [&](int p, float4 pa[2], float4 pb[2]) {
        float* Ash = smg + p * GBUF;
        float* Asl = Ash + GSLOT;
        float* Bsh = Asl + GSLOT;
        float* Bsl = Bsh + GSLOT;
#pragma unroll
        for (int it = 0; it < 2; it++) {
            int f   = tid + it * 256;
            int row = f >> 2;
            int c4  = (f & 3) * 4;
            float4 av = pa[it], bv = pb[it];
            float4 ah4, al4, bh4, bl4;
            split_tf32(av.x, ah4.x, al4.x); split_tf32(av.y, ah4.y, al4.y);
            split_tf32(av.z, ah4.z, al4.z); split_tf32(av.w, ah4.w, al4.w);
            split_tf32(bv.x, bh4.x, bl4.x); split_tf32(bv.y, bh4.y, bl4.y);
            split_tf32(bv.z, bh4.z, bl4.z); split_tf32(bv.w, bh4.w, bl4.w);
            *(float4*)(Ash + row * LDA + c4) = ah4;
            *(float4*)(Asl + row * LDA + c4) = al4;
            *(float4*)(Bsh + row * LDA + c4) = bh4;
            *(float4*)(Bsl + row * LDA + c4) = bl4;
        }
    };

    float4 pa[2], pb[2];
#pragma unroll
    for (int it = 0; it < 2; it++) load_g(0, it, pa[it], pb[it]);
    stage(0, pa, pb);
    __syncthreads();

    int p = 0;
#pragma unroll 1
    for (int kt = 0; kt < K; kt += BK) {
        const bool more = (kt + BK < K);
        // ---- issue next tile's global loads (retire under MMA phase) ----
        if (more) {
#pragma unroll
            for (int it = 0; it < 2; it++) load_g(kt + BK, it, pa[it], pb[it]);
        }

        // ---- MMA phase on buffer p: 3 low-pressure fragment passes ----
        const float* Ash = smg + p * GBUF;
        const float* Asl = Ash + GSLOT;
        const float* Bsh = Asl + GSLOT;
        const float* Bsl = Bsh + GSLOT;
#pragma unroll
        for (int ks = 0; ks < 2; ks++) {
            const int cb = ks * 8 + cq;
            unsigned fa[4][4], fb[4][2];

            // load B-hi fragments
#pragma unroll
            for (int ni = 0; ni < 4; ni++) {
                int rb = wn + ni * 8 + r0;
                fb[ni][0] = __float_as_uint(Bsh[rb * LDA + cb]);
                fb[ni][1] = __float_as_uint(Bsh[rb * LDA + cb + 4]);
            }
            // pass 1: A-lo x B-hi
#pragma unroll
            for (int mi = 0; mi < 4; mi++) {
                int rb = wm + mi * 16 + r0;
                fa[mi][0] = __float_as_uint(Asl[rb * LDA + cb]);
                fa[mi][1] = __float_as_uint(Asl[(rb + 8) * LDA + cb]);
                fa[mi][2] = __float_as_uint(Asl[rb * LDA + cb + 4]);
                fa[mi][3] = __float_as_uint(Asl[(rb + 8) * LDA + cb + 4]);
            }
#pragma unroll
            for (int mi = 0; mi < 4; mi++)
#pragma unroll
                for (int ni = 0; ni < 4; ni++)
                    mma8(acc[mi][ni], fa[mi][0], fa[mi][1], fa[mi][2], fa[mi][3],
                         fb[ni][0], fb[ni][1]);

            // pass 2: A-hi x B-hi (reload fa; fb kept)
#pragma unroll
            for (int mi = 0; mi < 4; mi++) {
                int rb = wm + mi * 16 + r0;
                fa[mi][0] = __float_as_uint(Ash[rb * LDA + cb]);
                fa[mi][1] = __float_as_uint(Ash[(rb + 8) * LDA + cb]);
                fa[mi][2] = __float_as_uint(Ash[rb * LDA + cb + 4]);
                fa[mi][3] = __float_as_uint(Ash[(rb + 8) * LDA + cb + 4]);
            }
#pragma unroll
            for (int mi = 0; mi < 4; mi++)
#pragma unroll
                for (int ni = 0; ni < 4; ni++)
                    mma8(acc[mi][ni], fa[mi][0], fa[mi][1], fa[mi][2], fa[mi][3],
                         fb[ni][0], fb[ni][1]);

            // pass 3: A-hi x B-lo (reload fb; fa kept)
#pragma unroll
            for (int ni = 0; ni < 4; ni++) {
                int rb = wn + ni * 8 + r0;
                fb[ni][0] = __float_as_uint(Bsl[rb * LDA + cb]);
                fb[ni][1] = __float_as_uint(Bsl[rb * LDA + cb + 4]);
            }
#pragma unroll
            for (int mi = 0; mi < 4; mi++)
#pragma unroll
                for (int ni = 0; ni < 4; ni++)
                    mma8(acc[mi][ni], fa[mi][0], fa[mi][1], fa[mi][2], fa[mi][3],
                         fb[ni][0], fb[ni][1]);
        }

        // ---- stage next tile into the inactive buffer, then single barrier ----
        if (more) stage(p ^ 1, pa, pb);
        __syncthreads();
        p ^= 1;
    }

    // ---- epilogue ----
#pragma unroll
    for (int mi = 0; mi < 4; mi++) {
#pragma unroll
        for (int ni = 0; ni < 4; ni++) {
            int rg = bm + wm + mi * 16 + r0;
            int cg = bn + wn + ni * 8 + cq * 2;
            float2 p0 = make_float2(acc[mi][ni][0], acc[mi][ni][1]);
            float2 p1 = make_float2(acc[mi][ni][2], acc[mi][ni][3]);
            if (CMODE == 0) {
                *(float2*)(C + (size_t)rg * N + cg)       = p0;
                *(float2*)(C + (size_t)(rg + 8) * N + cg) = p1;
            } else {
                int b_ = rg >> 11, s = rg & 2047;
                int h = cg >> 6, d = cg & 63;
                float* dst = C + ((size_t)((b_ * HEADS + h) * SEQ + s)) * DK + d;
                *(float2*)dst            = p0;
                *(float2*)(dst + 8 * DK) = p1;
            }
        }
    }
}

__global__ void __launch_bounds__(256, 2)
proj_kernel(const float* __restrict__ q, const float* __restrict__ k,
            const float* __restrict__ v, const float* __restrict__ Wq,
            const float* __restrict__ Wk, const float* __restrict__ Wv) {
    int z = blockIdx.z;
    const float* A = (z == 0) ? q : (z == 1) ? k : v;
    const float* W = (z == 0) ? Wq : (z == 1) ? Wk : Wv;
    float* Cg = (z == 0) ? g_Qh : (z == 1) ? g_Kh : g_Vh;
    gemm_body<0, 1>(A, W, Cg);
}

__global__ void __launch_bounds__(256, 2)
out_kernel(const float* __restrict__ Wo, float* __restrict__ out) {
    gemm_body<1, 0>(g_Oh, Wo, out);
}

// ---------------------------------------------------------------------------
// Flash attention: block = 128 q-rows of one (b,h), 8 warps x 16 rows.
// Key tiles of 64. Q in registers (scaled by 1/8), K split hi/lo (2xTF32 QK^T),
// P/V single tf32. Online softmax in fp32.
// R3: next K/V tile prefetched into registers during the MMA+softmax phase.
// R5: K/V smem double-buffered -> single __syncthreads per key tile.
// ---------------------------------------------------------------------------
constexpr int ALK = 68, ALV = 72, ALP = 68;        // padded strides (floats)
constexpr int AKBUF = 64 * ALK * 2 + 64 * ALV;     // Ksh+Ksl+Vs per buffer (floats)
constexpr size_t ATT_SHM = (size_t)(2 * AKBUF + 128 * ALP) * sizeof(float) +
                           2 * 64 * sizeof(int);   // ~141 KB

__global__ void __launch_bounds__(256)
attn_kernel(const int* __restrict__ mask) {
    constexpr int BQ = 128, BKEY = 64;
    constexpr int LK = ALK, LV = ALV, LP = ALP;

    extern __shared__ float sm[];
    // [buf0: Ksh|Ksl|Vs][buf1: Ksh|Ksl|Vs][Ps][msk0|msk1]
    float* Ps  = sm + 2 * AKBUF;          // 128 x LP
    int*   msk = (int*)(Ps + 128 * LP);   // 2 x 64

    const int tid  = threadIdx.x;
    const int lane = tid & 31;
    const int warp = tid >> 5;
    const int r0 = lane >> 2;
    const int cq = lane & 3;
    const int wrow = warp * 16;

    const int bh = blockIdx.y;       // b*H + h
    const int b_ = bh >> 4;
    const int q0 = blockIdx.x * BQ;

    const float* Qg = g_Qh + (size_t)bh * SEQ * DK;
    const float* Kg = g_Kh + (size_t)bh * SEQ * DK;
    const float* Vg = g_Vh + (size_t)bh * SEQ * DK;
    float*       Og = g_Oh + (size_t)bh * SEQ * DK;
    const int*   mg = mask + b_ * SEQ;

    // Q fragments, 1/sqrt(dk) folded in.  qa[ks][{r0,c},{r0+8,c},{r0,c+4},{r0+8,c+4}]
    unsigned qa[8][4];
    {
        const float* qr  = Qg + (size_t)(q0 + wrow + r0) * DK;
        const float* qr8 = qr + 8 * DK;
#pragma unroll
        for (int ks = 0; ks < 8; ks++) {
            int c = ks * 8 + cq;
            qa[ks][0] = f2tf(qr[c] * 0.125f);
            qa[ks][1] = f2tf(qr8[c] * 0.125f);
            qa[ks][2] = f2tf(qr[c + 4] * 0.125f);
            qa[ks][3] = f2tf(qr8[c + 4] * 0.125f);
        }
    }

    // --- K/V tile prefetch state (4 slots of float4 each) ---
    const int pr_row = tid >> 4;          // 0..15 (+16 per slot)
    const int pr_c4  = (tid & 15) * 4;    // 0..60
    float4 pk[4], pv[4];
    int    pm;
    auto load_kv = [&](int kt) {
#pragma unroll
        for (int it = 0; it < 4; it++) {
            int row = pr_row + it * 16;
            pk[it] = *(const float4*)(Kg + (size_t)(kt + row) * DK + pr_c4);
            pv[it] = *(const float4*)(Vg + (size_t)(kt + row) * DK + pr_c4);
        }
        pm = (tid < 64) ? mg[kt + tid] : 0;
    };

    // --- split prefetch regs into K/V buffer p ---
    auto stage_kv = [&](int p) {
        float* Ksh = sm + p * AKBUF;
        float* Ksl = Ksh + 64 * LK;
        float* Vs  = Ksl + 64 * LK;
#pragma unroll
        for (int it = 0; it < 4; it++) {
            int row = pr_row + it * 16;
            float4 kv = pk[it];
            float4 vv = pv[it];
            float4 kh4, kl4, vt;
            split_tf32(kv.x, kh4.x, kl4.x); split_tf32(kv.y, kh4.y, kl4.y);
            split_tf32(kv.z, kh4.z, kl4.z); split_tf32(kv.w, kh4.w, kl4.w);
            vt.x = __uint_as_float(f2tf(vv.x)); vt.y = __uint_as_float(f2tf(vv.y));
            vt.z = __uint_as_float(f2tf(vv.z)); vt.w = __uint_as_float(f2tf(vv.w));
            *(float4*)(Ksh + row * LK + pr_c4) = kh4;
            *(float4*)(Ksl + row * LK + pr_c4) = kl4;
            *(float4*)(Vs + row * LV + pr_c4)  = vt;
        }
        if (tid < 64) msk[p * 64 + tid] = pm;
    };

    load_kv(0);
    stage_kv(0);
    __syncthreads();

    float m0 = -1e30f, m1 = -1e30f, l0 = 0.f, l1 = 0.f;
    float o[8][4];
#pragma unroll
    for (int nf = 0; nf < 8; nf++)
#pragma unroll
        for (int t = 0; t < 4; t++) o[nf][t] = 0.f;

    int p = 0;
#pragma unroll 1
    for (int kt = 0; kt < SEQ; kt += BKEY) {
        const bool more = (kt + BKEY < SEQ);
        // ---- issue next tile's global loads (retire under MMA phase) ----
        if (more) load_kv(kt + BKEY);

        const float* Ksh = sm + p * AKBUF;
        const float* Ksl = Ksh + 64 * LK;
        const float* Vs  = Ksl + 64 * LK;
        const int*   mk  = msk + p * 64;

        // ---- S = Q K^T (2xTF32: q*k_lo + q*k_hi) ----
        float sacc[8][4];
#pragma unroll
        for (int nf = 0; nf < 8; nf++)
#pragma unroll
            for (int t = 0; t < 4; t++) sacc[nf][t] = 0.f;

#pragma unroll
        for (int ks = 0; ks < 8; ks++) {
#pragma unroll
            for (int nf = 0; nf < 8; nf++) {
                int rb = (nf * 8 + r0) * LK + ks * 8 + cq;
                unsigned kl0 = __float_as_uint(Ksl[rb]);
                unsigned kl1 = __float_as_uint(Ksl[rb + 4]);
                unsigned kh0 = __float_as_uint(Ksh[rb]);
                unsigned kh1 = __float_as_uint(Ksh[rb + 4]);
                mma8(sacc[nf], qa[ks][0], qa[ks][1], qa[ks][2], qa[ks][3], kl0, kl1);
                mma8(sacc[nf], qa[ks][0], qa[ks][1], qa[ks][2], qa[ks][3], kh0, kh1);
            }
        }

        // ---- mask + online softmax ----
        float mx0 = -1e30f, mx1 = -1e30f;
#pragma unroll
        for (int nf = 0; nf < 8; nf++) {
            int c = nf * 8 + cq * 2;
            if (mk[c] == 0)     { sacc[nf][0] = -1e9f; sacc[nf][2] = -1e9f; }
            if (mk[c + 1] == 0) { sacc[nf][1] = -1e9f; sacc[nf][3] = -1e9f; }
            mx0 = fmaxf(mx0, fmaxf(sacc[nf][0], sacc[nf][1]));
            mx1 = fmaxf(mx1, fmaxf(sacc[nf][2], sacc[nf][3]));
        }
        mx0 = fmaxf(mx0, __shfl_xor_sync(0xffffffffu, mx0, 1));
        mx0 = fmaxf(mx0, __shfl_xor_sync(0xffffffffu, mx0, 2));
        mx1 = fmaxf(mx1, __shfl_xor_sync(0xffffffffu, mx1, 1));
        mx1 = fmaxf(mx1, __shfl_xor_sync(0xffffffffu, mx1, 2));

        float mn0 = fmaxf(m0, mx0), mn1 = fmaxf(m1, mx1);
        float al0 = __expf(m0 - mn0), al1 = __expf(m1 - mn1);
        m0 = mn0; m1 = mn1;

        float rs0 = 0.f, rs1 = 0.f;
#pragma unroll
        for (int nf = 0; nf < 8; nf++) {
            sacc[nf][0] = __expf(sacc[nf][0] - m0);
            sacc[nf][1] = __expf(sacc[nf][1] - m0);
            sacc[nf][2] = __expf(sacc[nf][2] - m1);
            sacc[nf][3] = __expf(sacc[nf][3] - m1);
            rs0 += sacc[nf][0] + sacc[nf][1];
            rs1 += sacc[nf][2] + sacc[nf][3];
        }
        rs0 += __shfl_xor_sync(0xffffffffu, rs0, 1);
        rs0 += __shfl_xor_sync(0xffffffffu, rs0, 2);
        rs1 += __shfl_xor_sync(0xffffffffu, rs1, 1);
        rs1 += __shfl_xor_sync(0xffffffffu, rs1, 2);
        l0 = l0 * al0 + rs0;
        l1 = l1 * al1 + rs1;

#pragma unroll
        for (int nf = 0; nf < 8; nf++) {
            o[nf][0] *= al0; o[nf][1] *= al0;
            o[nf][2] *= al1; o[nf][3] *= al1;
        }

        // ---- write P (per-warp private rows; no cross-warp hazard) ----
#pragma unroll
        for (int nf = 0; nf < 8; nf++) {
            int c = nf * 8 + cq * 2;
            Ps[(wrow + r0) * LP + c]         = __uint_as_float(f2tf(sacc[nf][0]));
            Ps[(wrow + r0) * LP + c + 1]     = __uint_as_float(f2tf(sacc[nf][1]));
            Ps[(wrow + r0 + 8) * LP + c]     = __uint_as_float(f2tf(sacc[nf][2]));
            Ps[(wrow + r0 + 8) * LP + c + 1] = __uint_as_float(f2tf(sacc[nf][3]));
        }
        __syncwarp();

        // ---- O += P V ----
#pragma unroll
        for (int ks = 0; ks < 8; ks++) {
            int pc = ks * 8 + cq;
            unsigned pa0 = __float_as_uint(Ps[(wrow + r0) * LP + pc]);
            unsigned pa1 = __float_as_uint(Ps[(wrow + r0 + 8) * LP + pc]);
            unsigned pa2 = __float_as_uint(Ps[(wrow + r0) * LP + pc + 4]);
            unsigned pa3 = __float_as_uint(Ps[(wrow + r0 + 8) * LP + pc + 4]);
#pragma unroll
            for (int nf = 0; nf < 8; nf++) {
                int vb = (ks * 8 + cq) * LV + nf * 8 + r0;
                unsigned v0 = __float_as_uint(Vs[vb]);
                unsigned v1 = __float_as_uint(Vs[vb + 4 * LV]);
                mma8(o[nf], pa0, pa1, pa2, pa3, v0, v1);
            }
        }

        // ---- stage next tile into the inactive buffer, then single barrier ----
        if (more) stage_kv(p ^ 1);
        __syncthreads();
        p ^= 1;
    }

    // ---- epilogue: divide by l, store to g_Oh ----
    float i0 = 1.f / l0, i1 = 1.f / l1;
    int qr = q0 + wrow + r0;
#pragma unroll
    for (int nf = 0; nf < 8; nf++) {
        int d = nf * 8 + cq * 2;
        float2 p0 = make_float2(o[nf][0] * i0, o[nf][1] * i0);
        float2 p1 = make_float2(o[nf][2] * i1, o[nf][3] * i1);
        *(float2*)(Og + (size_t)qr * DK + d)       = p0;
        *(float2*)(Og + (size_t)(qr + 8) * DK + d) = p1;
    }
}

// ---------------------------------------------------------------------------
extern "C" void kernel_launch(void* const* d_in, const int* in_sizes, int n_in,
                              void* d_out, int out_size) {
    const float* q    = (const float*)d_in[0];
    const float* k    = (const float*)d_in[1];
    const float* v    = (const float*)d_in[2];
    const int*   mask = (const int*)d_in[3];
    const float* Wq   = (const float*)d_in[4];
    const float* Wk   = (const float*)d_in[5];
    const float* Wv   = (const float*)d_in[6];
    const float* Wo   = (const float*)d_in[7];
    float* out = (float*)d_out;

    dim3 blk(256);

    // GEMM kernels: 80 KB dynamic smem (double-buffered, BK=16), 2 CTAs/SM
    cudaFuncSetAttribute(proj_kernel, cudaFuncAttributeMaxDynamicSharedMemorySize,
                         (int)GEMM_SHM);
    cudaFuncSetAttribute(out_kernel, cudaFuncAttributeMaxDynamicSharedMemorySize,
                         (int)GEMM_SHM);

    // Q/K/V projections (z selects which)
    proj_kernel<<<dim3(DMODEL / 128, NTOK / 128, 3), blk, GEMM_SHM>>>(q, k, v, Wq, Wk, Wv);

    // Attention (double-buffered K/V: ~141 KB dynamic smem)
    cudaFuncSetAttribute(attn_kernel, cudaFuncAttributeMaxDynamicSharedMemorySize,
                         (int)ATT_SHM);
    attn_kernel<<<dim3(SEQ / 128, BATCH * HEADS), blk, ATT_SHM>>>(mask);

    // Output projection
    out_kernel<<<dim3(DMODEL / 128, NTOK / 128), blk, GEMM_SHM>>>(Wo, out);
}

// round 10
// speedup vs baseline: 1.1440x; 1.1440x over previous
#include <cuda_runtime.h>

// ---------------------------------------------------------------------------
// MultiHeadAttention: out = softmax((X Wq^T)(X Wk^T)^T / sqrt(dk) + mask) (X Wv^T) Wo^T
// B=2, S=2048, D_MODEL=1024, H=16, DK=64
// R1: register-prefetch pipeline in gemm_body.
// R2: double-buffered smem in gemm_body -> one __syncthreads per K-step.
// R3: register-prefetch of next K/V tile in attn_kernel.
// R5: double-buffered K/V smem in attn_kernel.
// R6: GEMM BK=16 + __launch_bounds__(256,2): 2 CTAs/SM (verified occ=23%).
// R7: GEMM MMA phase in low-pressure fragment passes (no spill at 128 regs).
// R8 (measured): 995.1us, rel_err 3.54e-4; proj tensor=57.7% L1=60.1%.
// R9/R10: dense GEMMs 3xTF32 -> 2xTF32 (split weights only, single-round
//     activations): -33% on BOTH co-bound pipes. Predicted ~810us, ~6e-4.
//     (R9 submission never ran - broker timeout; re-benching unchanged.)
// ---------------------------------------------------------------------------

constexpr int DMODEL = 1024;
constexpr int HEADS  = 16;
constexpr int DK     = 64;
constexpr int BATCH  = 2;
constexpr int SEQ    = 2048;
constexpr int NTOK   = BATCH * SEQ;   // 4096

// Scratch (head-split layout [B,H,S,DK])
__device__ float g_Qh[NTOK * DMODEL];
__device__ float g_Kh[NTOK * DMODEL];
__device__ float g_Vh[NTOK * DMODEL];
__device__ float g_Oh[NTOK * DMODEL];

__device__ __forceinline__ unsigned f2tf(float x) {
    unsigned r;
    asm("cvt.rna.tf32.f32 %0, %1;" : "=r"(r) : "f"(x));
    return r;
}

__device__ __forceinline__ void split_tf32(float x, float& hi, float& lo) {
    hi = __uint_as_float(f2tf(x));
    lo = __uint_as_float(f2tf(x - hi));
}

// D = A(16x8) * B(8x8) + D, tf32
__device__ __forceinline__ void mma8(float c[4], unsigned a0, unsigned a1,
                                     unsigned a2, unsigned a3,
                                     unsigned b0, unsigned b1) {
    asm("mma.sync.aligned.m16n8k8.row.col.f32.tf32.tf32.f32 "
        "{%0,%1,%2,%3},{%4,%5,%6,%7},{%8,%9},{%0,%1,%2,%3};"
        : "+f"(c[0]), "+f"(c[1]), "+f"(c[2]), "+f"(c[3])
        : "r"(a0), "r"(a1), "r"(a2), "r"(a3), "r"(b0), "r"(b1));
}

// ---------------------------------------------------------------------------
// Generic NT GEMM: C[M,N] = A[M,K] * Bw[N,K]^T with 2xTF32:
//   A single-rounded to tf32 (As); weights split hi/lo (Bsh, Bsl);
//   acc += a*bl then acc += a*bh.
// AMODE 0: A plain row-major [M,K].  AMODE 1: A gathered from [B,H,S,DK].
// CMODE 0: C plain row-major [M,N].  CMODE 1: C scattered to [B,H,S,DK].
// Block: 256 threads, tile 128x128, BK=16. Warps 2x4, each 64x32.
// Double-buffered dynamic smem (60 KB) + register prefetch; 2 CTAs/SM.
// ---------------------------------------------------------------------------
constexpr int GBM = 128, GBN = 128, GBK = 16, GLDA = 20;  // stride 20: conflict-free
constexpr int GSLOT = GBM * GLDA;            // one array (floats)
constexpr int GBUF  = 3 * GSLOT;             // As,Bsh,Bsl (floats)
constexpr size_t GEMM_SHM = (size_t)2 * GBUF * sizeof(float);  // 61440 B

template <int AMODE, int CMODE>
__device__ __forceinline__ void gemm_body(const float* __restrict__ A,
                                          const float* __restrict__ Bw,
                                          float* __restrict__ C) {
    constexpr int BM = GBM, BN = GBN, BK = GBK, LDA = GLDA;
    constexpr int K = DMODEL, N = DMODEL;

    extern __shared__ float smg[];

    const int tid  = threadIdx.x;
    const int lane = tid & 31;
    const int warp = tid >> 5;
    const int wm = (warp >> 2) * 64;  // warp row offset in tile
    const int wn = (warp & 3) * 32;   // warp col offset in tile
    const int bm = blockIdx.y * BM;
    const int bn = blockIdx.x * BN;
    const int r0 = lane >> 2;         // 0..7
    const int cq = lane & 3;          // 0..3

    float acc[4][4][4];
#pragma unroll
    for (int i = 0; i < 4; i++)
#pragma unroll
        for (int j = 0; j < 4; j++)
#pragma unroll
            for (int t = 0; t < 4; t++) acc[i][j][t] = 0.f;

    // --- global loader for one staging slot (it = 0,1) ---
    auto load_g = [&](int kt, int it, float4& av, float4& bv) {
        int f   = tid + it * 256;      // 0..511
        int row = f >> 2;              // 0..127
        int c4  = (f & 3) * 4;         // 0..12
        if (AMODE == 0) {
            av = *(const float4*)(A + (size_t)(bm + row) * K + kt + c4);
        } else {
            int ig = bm + row;
            int b_ = ig >> 11, s = ig & 2047;
            int k0 = kt + c4;
            int h = k0 >> 6, d = k0 & 63;
            av = *(const float4*)(A + ((size_t)((b_ * HEADS + h) * SEQ + s)) * DK + d);
        }
        bv = *(const float4*)(Bw + (size_t)(bn + row) * K + kt + c4);
    };

    // --- convert prefetched regs and store into buffer p ---
    auto stage = [&](int p, float4 pa[2], float4 pb[2]) {
        float* As  = smg + p * GBUF;
        float* Bsh = As + GSLOT;
        float* Bsl = Bsh + GSLOT;
#pragma unroll
        for (int it = 0; it < 2; it++) {
            int f   = tid + it * 256;
            int row = f >> 2;
            int c4  = (f & 3) * 4;
            float4 av = pa[it], bv = pb[it];
            float4 at4, bh4, bl4;
            at4.x = __uint_as_float(f2tf(av.x)); at4.y = __uint_as_float(f2tf(av.y));
            at4.z = __uint_as_float(f2tf(av.z)); at4.w = __uint_as_float(f2tf(av.w));
            split_tf32(bv.x, bh4.x, bl4.x); split_tf32(bv.y, bh4.y, bl4.y);
            split_tf32(bv.z, bh4.z, bl4.z); split_tf32(bv.w, bh4.w, bl4.w);
            *(float4*)(As  + row * LDA + c4) = at4;
            *(float4*)(Bsh + row * LDA + c4) = bh4;
            *(float4*)(Bsl + row * LDA + c4) = bl4;
        }
    };

    float4 pa[2], pb[2];
#pragma unroll
    for (int it = 0; it < 2; it++) load_g(0, it, pa[it], pb[it]);
    stage(0, pa, pb);
    __syncthreads();

    int p = 0;
#pragma unroll 1
    for (int kt = 0; kt < K; kt += BK) {
        const bool more = (kt + BK < K);
        // ---- issue next tile's global loads (retire under MMA phase) ----
        if (more) {
#pragma unroll
            for (int it = 0; it < 2; it++) load_g(kt + BK, it, pa[it], pb[it]);
        }

        // ---- MMA phase on buffer p: 2 passes (a*bl, a*bh) ----
        const float* As  = smg + p * GBUF;
        const float* Bsh = As + GSLOT;
        const float* Bsl = Bsh + GSLOT;
#pragma unroll
        for (int ks = 0; ks < 2; ks++) {
            const int cb = ks * 8 + cq;
            unsigned fa[4][4], fb[4][2];

            // load A fragments (single tf32)
#pragma unroll
            for (int mi = 0; mi < 4; mi++) {
                int rb = wm + mi * 16 + r0;
                fa[mi][0] = __float_as_uint(As[rb * LDA + cb]);
                fa[mi][1] = __float_as_uint(As[(rb + 8) * LDA + cb]);
                fa[mi][2] = __float_as_uint(As[rb * LDA + cb + 4]);
                fa[mi][3] = __float_as_uint(As[(rb + 8) * LDA + cb + 4]);
            }
            // pass 1: A x B-lo
#pragma unroll
            for (int ni = 0; ni < 4; ni++) {
                int rb = wn + ni * 8 + r0;
                fb[ni][0] = __float_as_uint(Bsl[rb * LDA + cb]);
                fb[ni][1] = __float_as_uint(Bsl[rb * LDA + cb + 4]);
            }
#pragma unroll
            for (int mi = 0; mi < 4; mi++)
#pragma unroll
                for (int ni = 0; ni < 4; ni++)
                    mma8(acc[mi][ni], fa[mi][0], fa[mi][1], fa[mi][2], fa[mi][3],
                         fb[ni][0], fb[ni][1]);

            // pass 2: A x B-hi (reload fb; fa kept)
#pragma unroll
            for (int ni = 0; ni < 4; ni++) {
                int rb = wn + ni * 8 + r0;
                fb[ni][0] = __float_as_uint(Bsh[rb * LDA + cb]);
                fb[ni][1] = __float_as_uint(Bsh[rb * LDA + cb + 4]);
            }
#pragma unroll
            for (int mi = 0; mi < 4; mi++)
#pragma unroll
                for (int ni = 0; ni < 4; ni++)
                    mma8(acc[mi][ni], fa[mi][0], fa[mi][1], fa[mi][2], fa[mi][3],
                         fb[ni][0], fb[ni][1]);
        }

        // ---- stage next tile into the inactive buffer, then single barrier ----
        if (more) stage(p ^ 1, pa, pb);
        __syncthreads();
        p ^= 1;
    }

    // ---- epilogue ----
#pragma unroll
    for (int mi = 0; mi < 4; mi++) {
#pragma unroll
        for (int ni = 0; ni < 4; ni++) {
            int rg = bm + wm + mi * 16 + r0;
            int cg = bn + wn + ni * 8 + cq * 2;
            float2 p0 = make_float2(acc[mi][ni][0], acc[mi][ni][1]);
            float2 p1 = make_float2(acc[mi][ni][2], acc[mi][ni][3]);
            if (CMODE == 0) {
                *(float2*)(C + (size_t)rg * N + cg)       = p0;
                *(float2*)(C + (size_t)(rg + 8) * N + cg) = p1;
            } else {
                int b_ = rg >> 11, s = rg & 2047;
                int h = cg >> 6, d = cg & 63;
                float* dst = C + ((size_t)((b_ * HEADS + h) * SEQ + s)) * DK + d;
                *(float2*)dst            = p0;
                *(float2*)(dst + 8 * DK) = p1;
            }
        }
    }
}

__global__ void __launch_bounds__(256, 2)
proj_kernel(const float* __restrict__ q, const float* __restrict__ k,
            const float* __restrict__ v, const float* __restrict__ Wq,
            const float* __restrict__ Wk, const float* __restrict__ Wv) {
    int z = blockIdx.z;
    const float* A = (z == 0) ? q : (z == 1) ? k : v;
    const float* W = (z == 0) ? Wq : (z == 1) ? Wk : Wv;
    float* Cg = (z == 0) ? g_Qh : (z == 1) ? g_Kh : g_Vh;
    gemm_body<0, 1>(A, W, Cg);
}

__global__ void __launch_bounds__(256, 2)
out_kernel(const float* __restrict__ Wo, float* __restrict__ out) {
    gemm_body<1, 0>(g_Oh, Wo, out);
}

// ---------------------------------------------------------------------------
// Flash attention: block = 128 q-rows of one (b,h), 8 warps x 16 rows.
// Key tiles of 64. Q in registers (scaled by 1/8), K split hi/lo (2xTF32 QK^T),
// P/V single tf32. Online softmax in fp32.
// R3: next K/V tile prefetched into registers during the MMA+softmax phase.
// R5: K/V smem double-buffered -> single __syncthreads per key tile.
// ---------------------------------------------------------------------------
constexpr int ALK = 68, ALV = 72, ALP = 68;        // padded strides (floats)
constexpr int AKBUF = 64 * ALK * 2 + 64 * ALV;     // Ksh+Ksl+Vs per buffer (floats)
constexpr size_t ATT_SHM = (size_t)(2 * AKBUF + 128 * ALP) * sizeof(float) +
                           2 * 64 * sizeof(int);   // ~141 KB

__global__ void __launch_bounds__(256)
attn_kernel(const int* __restrict__ mask) {
    constexpr int BQ = 128, BKEY = 64;
    constexpr int LK = ALK, LV = ALV, LP = ALP;

    extern __shared__ float sm[];
    // [buf0: Ksh|Ksl|Vs][buf1: Ksh|Ksl|Vs][Ps][msk0|msk1]
    float* Ps  = sm + 2 * AKBUF;          // 128 x LP
    int*   msk = (int*)(Ps + 128 * LP);   // 2 x 64

    const int tid  = threadIdx.x;
    const int lane = tid & 31;
    const int warp = tid >> 5;
    const int r0 = lane >> 2;
    const int cq = lane & 3;
    const int wrow = warp * 16;

    const int bh = blockIdx.y;       // b*H + h
    const int b_ = bh >> 4;
    const int q0 = blockIdx.x * BQ;

    const float* Qg = g_Qh + (size_t)bh * SEQ * DK;
    const float* Kg = g_Kh + (size_t)bh * SEQ * DK;
    const float* Vg = g_Vh + (size_t)bh * SEQ * DK;
    float*       Og = g_Oh + (size_t)bh * SEQ * DK;
    const int*   mg = mask + b_ * SEQ;

    // Q fragments, 1/sqrt(dk) folded in.  qa[ks][{r0,c},{r0+8,c},{r0,c+4},{r0+8,c+4}]
    unsigned qa[8][4];
    {
        const float* qr  = Qg + (size_t)(q0 + wrow + r0) * DK;
        const float* qr8 = qr + 8 * DK;
#pragma unroll
        for (int ks = 0; ks < 8; ks++) {
            int c = ks * 8 + cq;
            qa[ks][0] = f2tf(qr[c] * 0.125f);
            qa[ks][1] = f2tf(qr8[c] * 0.125f);
            qa[ks][2] = f2tf(qr[c + 4] * 0.125f);
            qa[ks][3] = f2tf(qr8[c + 4] * 0.125f);
        }
    }

    // --- K/V tile prefetch state (4 slots of float4 each) ---
    const int pr_row = tid >> 4;          // 0..15 (+16 per slot)
    const int pr_c4  = (tid & 15) * 4;    // 0..60
    float4 pk[4], pv[4];
    int    pm;
    auto load_kv = [&](int kt) {
#pragma unroll
        for (int it = 0; it < 4; it++) {
            int row = pr_row + it * 16;
            pk[it] = *(const float4*)(Kg + (size_t)(kt + row) * DK + pr_c4);
            pv[it] = *(const float4*)(Vg + (size_t)(kt + row) * DK + pr_c4);
        }
        pm = (tid < 64) ? mg[kt + tid] : 0;
    };

    // --- split prefetch regs into K/V buffer p ---
    auto stage_kv = [&](int p) {
        float* Ksh = sm + p * AKBUF;
        float* Ksl = Ksh + 64 * LK;
        float* Vs  = Ksl + 64 * LK;
#pragma unroll
        for (int it = 0; it < 4; it++) {
            int row = pr_row + it * 16;
            float4 kv = pk[it];
            float4 vv = pv[it];
            float4 kh4, kl4, vt;
            split_tf32(kv.x, kh4.x, kl4.x); split_tf32(kv.y, kh4.y, kl4.y);
            split_tf32(kv.z, kh4.z, kl4.z); split_tf32(kv.w, kh4.w, kl4.w);
            vt.x = __uint_as_float(f2tf(vv.x)); vt.y = __uint_as_float(f2tf(vv.y));
            vt.z = __uint_as_float(f2tf(vv.z)); vt.w = __uint_as_float(f2tf(vv.w));
            *(float4*)(Ksh + row * LK + pr_c4) = kh4;
            *(float4*)(Ksl + row * LK + pr_c4) = kl4;
            *(float4*)(Vs + row * LV + pr_c4)  = vt;
        }
        if (tid < 64) msk[p * 64 + tid] = pm;
    };

    load_kv(0);
    stage_kv(0);
    __syncthreads();

    float m0 = -1e30f, m1 = -1e30f, l0 = 0.f, l1 = 0.f;
    float o[8][4];
#pragma unroll
    for (int nf = 0; nf < 8; nf++)
#pragma unroll
        for (int t = 0; t < 4; t++) o[nf][t] = 0.f;

    int p = 0;
#pragma unroll 1
    for (int kt = 0; kt < SEQ; kt += BKEY) {
        const bool more = (kt + BKEY < SEQ);
        // ---- issue next tile's global loads (retire under MMA phase) ----
        if (more) load_kv(kt + BKEY);

        const float* Ksh = sm + p * AKBUF;
        const float* Ksl = Ksh + 64 * LK;
        const float* Vs  = Ksl + 64 * LK;
        const int*   mk  = msk + p * 64;

        // ---- S = Q K^T (2xTF32: q*k_lo + q*k_hi) ----
        float sacc[8][4];
#pragma unroll
        for (int nf = 0; nf < 8; nf++)
#pragma unroll
            for (int t = 0; t < 4; t++) sacc[nf][t] = 0.f;

#pragma unroll
        for (int ks = 0; ks < 8; ks++) {
#pragma unroll
            for (int nf = 0; nf < 8; nf++) {
                int rb = (nf * 8 + r0) * LK + ks * 8 + cq;
                unsigned kl0 = __float_as_uint(Ksl[rb]);
                unsigned kl1 = __float_as_uint(Ksl[rb + 4]);
                unsigned kh0 = __float_as_uint(Ksh[rb]);
                unsigned kh1 = __float_as_uint(Ksh[rb + 4]);
                mma8(sacc[nf], qa[ks][0], qa[ks][1], qa[ks][2], qa[ks][3], kl0, kl1);
                mma8(sacc[nf], qa[ks][0], qa[ks][1], qa[ks][2], qa[ks][3], kh0, kh1);
            }
        }

        // ---- mask + online softmax ----
        float mx0 = -1e30f, mx1 = -1e30f;
#pragma unroll
        for (int nf = 0; nf < 8; nf++) {
            int c = nf * 8 + cq * 2;
            if (mk[c] == 0)     { sacc[nf][0] = -1e9f; sacc[nf][2] = -1e9f; }
            if (mk[c + 1] == 0) { sacc[nf][1] = -1e9f; sacc[nf][3] = -1e9f; }
            mx0 = fmaxf(mx0, fmaxf(sacc[nf][0], sacc[nf][1]));
            mx1 = fmaxf(mx1, fmaxf(sacc[nf][2], sacc[nf][3]));
        }
        mx0 = fmaxf(mx0, __shfl_xor_sync(0xffffffffu, mx0, 1));
        mx0 = fmaxf(mx0, __shfl_xor_sync(0xffffffffu, mx0, 2));
        mx1 = fmaxf(mx1, __shfl_xor_sync(0xffffffffu, mx1, 1));
        mx1 = fmaxf(mx1, __shfl_xor_sync(0xffffffffu, mx1, 2));

        float mn0 = fmaxf(m0, mx0), mn1 = fmaxf(m1, mx1);
        float al0 = __expf(m0 - mn0), al1 = __expf(m1 - mn1);
        m0 = mn0; m1 = mn1;

        float rs0 = 0.f, rs1 = 0.f;
#pragma unroll
        for (int nf = 0; nf < 8; nf++) {
            sacc[nf][0] = __expf(sacc[nf][0] - m0);
            sacc[nf][1] = __expf(sacc[nf][1] - m0);
            sacc[nf][2] = __expf(sacc[nf][2] - m1);
            sacc[nf][3] = __expf(sacc[nf][3] - m1);
            rs0 += sacc[nf][0] + sacc[nf][1];
            rs1 += sacc[nf][2] + sacc[nf][3];
        }
        rs0 += __shfl_xor_sync(0xffffffffu, rs0, 1);
        rs0 += __shfl_xor_sync(0xffffffffu, rs0, 2);
        rs1 += __shfl_xor_sync(0xffffffffu, rs1, 1);
        rs1 += __shfl_xor_sync(0xffffffffu, rs1, 2);
        l0 = l0 * al0 + rs0;
        l1 = l1 * al1 + rs1;

#pragma unroll
        for (int nf = 0; nf < 8; nf++) {
            o[nf][0] *= al0; o[nf][1] *= al0;
            o[nf][2] *= al1; o[nf][3] *= al1;
        }

        // ---- write P (per-warp private rows; no cross-warp hazard) ----
#pragma unroll
        for (int nf = 0; nf < 8; nf++) {
            int c = nf * 8 + cq * 2;
            Ps[(wrow + r0) * LP + c]         = __uint_as_float(f2tf(sacc[nf][0]));
            Ps[(wrow + r0) * LP + c + 1]     = __uint_as_float(f2tf(sacc[nf][1]));
            Ps[(wrow + r0 + 8) * LP + c]     = __uint_as_float(f2tf(sacc[nf][2]));
            Ps[(wrow + r0 + 8) * LP + c + 1] = __uint_as_float(f2tf(sacc[nf][3]));
        }
        __syncwarp();

        // ---- O += P V ----
#pragma unroll
        for (int ks = 0; ks < 8; ks++) {
            int pc = ks * 8 + cq;
            unsigned pa0 = __float_as_uint(Ps[(wrow + r0) * LP + pc]);
            unsigned pa1 = __float_as_uint(Ps[(wrow + r0 + 8) * LP + pc]);
            unsigned pa2 = __float_as_uint(Ps[(wrow + r0) * LP + pc + 4]);
            unsigned pa3 = __float_as_uint(Ps[(wrow + r0 + 8) * LP + pc + 4]);
#pragma unroll
            for (int nf = 0; nf < 8; nf++) {
                int vb = (ks * 8 + cq) * LV + nf * 8 + r0;
                unsigned v0 = __float_as_uint(Vs[vb]);
                unsigned v1 = __float_as_uint(Vs[vb + 4 * LV]);
                mma8(o[nf], pa0, pa1, pa2, pa3, v0, v1);
            }
        }

        // ---- stage next tile into the inactive buffer, then single barrier ----
        if (more) stage_kv(p ^ 1);
        __syncthreads();
        p ^= 1;
    }

    // ---- epilogue: divide by l, store to g_Oh ----
    float i0 = 1.f / l0, i1 = 1.f / l1;
    int qr = q0 + wrow + r0;
#pragma unroll
    for (int nf = 0; nf < 8; nf++) {
        int d = nf * 8 + cq * 2;
        float2 p0 = make_float2(o[nf][0] * i0, o[nf][1] * i0);
        float2 p1 = make_float2(o[nf][2] * i1, o[nf][3] * i1);
        *(float2*)(Og + (size_t)qr * DK + d)       = p0;
        *(float2*)(Og + (size_t)(qr + 8) * DK + d) = p1;
    }
}

// ---------------------------------------------------------------------------
extern "C" void kernel_launch(void* const* d_in, const int* in_sizes, int n_in,
                              void* d_out, int out_size) {
    const float* q    = (const float*)d_in[0];
    const float* k    = (const float*)d_in[1];
    const float* v    = (const float*)d_in[2];
    const int*   mask = (const int*)d_in[3];
    const float* Wq   = (const float*)d_in[4];
    const float* Wk   = (const float*)d_in[5];
    const float* Wv   = (const float*)d_in[6];
    const float* Wo   = (const float*)d_in[7];
    float* out = (float*)d_out;

    dim3 blk(256);

    // GEMM kernels: 60 KB dynamic smem (double-buffered, 2xTF32), 2 CTAs/SM
    cudaFuncSetAttribute(proj_kernel, cudaFuncAttributeMaxDynamicSharedMemorySize,
                         (int)GEMM_SHM);
    cudaFuncSetAttribute(out_kernel, cudaFuncAttributeMaxDynamicSharedMemorySize,
                         (int)GEMM_SHM);

    // Q/K/V projections (z selects which)
    proj_kernel<<<dim3(DMODEL / 128, NTOK / 128, 3), blk, GEMM_SHM>>>(q, k, v, Wq, Wk, Wv);

    // Attention (double-buffered K/V: ~141 KB dynamic smem)
    cudaFuncSetAttribute(attn_kernel, cudaFuncAttributeMaxDynamicSharedMemorySize,
                         (int)ATT_SHM);
    attn_kernel<<<dim3(SEQ / 128, BATCH * HEADS), blk, ATT_SHM>>>(mask);

    // Output projection
    out_kernel<<<dim3(DMODEL / 128, NTOK / 128), blk, GEMM_SHM>>>(Wo, out);
}

// round 16
// speedup vs baseline: 1.2516x; 1.0940x over previous
#include <cuda_runtime.h>

// ---------------------------------------------------------------------------
// MultiHeadAttention: out = softmax((X Wq^T)(X Wk^T)^T / sqrt(dk) + mask) (X Wv^T) Wo^T
// B=2, S=2048, D_MODEL=1024, H=16, DK=64
// R1/R2: pipelined + double-buffered GEMM.  R3/R5: same for attention.
// R6/R7: GEMM 2 CTAs/SM at 128 regs (low-pressure fragment passes).
// R8 (measured): 995.1us, rel_err 3.54e-4.
// R10 (measured): 869.9us, rel_err 5.47e-4; proj L1=57.6% tensor=48.8%
//     (crossbar-bound: LDS bytes, not instruction count, are the binder).
// R11..R16: QK^T 2xTF32 -> 1xTF32 (single-round K, no hi/lo split):
//     attn MMA passes 3->2, QK fragment LDS halved, smem 141->105 KB.
//     Predicted ~770us, rel_err ~6.5e-4.
//     (R11-R15 submissions never ran - broker timeouts; re-benching.)
// ---------------------------------------------------------------------------

constexpr int DMODEL = 1024;
constexpr int HEADS  = 16;
constexpr int DK     = 64;
constexpr int BATCH  = 2;
constexpr int SEQ    = 2048;
constexpr int NTOK   = BATCH * SEQ;   // 4096

// Scratch (head-split layout [B,H,S,DK])
__device__ float g_Qh[NTOK * DMODEL];
__device__ float g_Kh[NTOK * DMODEL];
__device__ float g_Vh[NTOK * DMODEL];
__device__ float g_Oh[NTOK * DMODEL];

__device__ __forceinline__ unsigned f2tf(float x) {
    unsigned r;
    asm("cvt.rna.tf32.f32 %0, %1;" : "=r"(r) : "f"(x));
    return r;
}

__device__ __forceinline__ void split_tf32(float x, float& hi, float& lo) {
    hi = __uint_as_float(f2tf(x));
    lo = __uint_as_float(f2tf(x - hi));
}

// D = A(16x8) * B(8x8) + D, tf32
__device__ __forceinline__ void mma8(float c[4], unsigned a0, unsigned a1,
                                     unsigned a2, unsigned a3,
                                     unsigned b0, unsigned b1) {
    asm("mma.sync.aligned.m16n8k8.row.col.f32.tf32.tf32.f32 "
        "{%0,%1,%2,%3},{%4,%5,%6,%7},{%8,%9},{%0,%1,%2,%3};"
        : "+f"(c[0]), "+f"(c[1]), "+f"(c[2]), "+f"(c[3])
        : "r"(a0), "r"(a1), "r"(a2), "r"(a3), "r"(b0), "r"(b1));
}

// ---------------------------------------------------------------------------
// Generic NT GEMM: C[M,N] = A[M,K] * Bw[N,K]^T with 2xTF32:
//   A single-rounded to tf32 (As); weights split hi/lo (Bsh, Bsl).
// AMODE 0: A plain row-major [M,K].  AMODE 1: A gathered from [B,H,S,DK].
// CMODE 0: C plain row-major [M,N].  CMODE 1: C scattered to [B,H,S,DK].
// Block: 256 threads, tile 128x128, BK=16. Warps 2x4, each 64x32.
// Double-buffered dynamic smem (60 KB) + register prefetch; 2 CTAs/SM.
// ---------------------------------------------------------------------------
constexpr int GBM = 128, GBN = 128, GBK = 16, GLDA = 20;  // stride 20: conflict-free
constexpr int GSLOT = GBM * GLDA;            // one array (floats)
constexpr int GBUF  = 3 * GSLOT;             // As,Bsh,Bsl (floats)
constexpr size_t GEMM_SHM = (size_t)2 * GBUF * sizeof(float);  // 61440 B

template <int AMODE, int CMODE>
__device__ __forceinline__ void gemm_body(const float* __restrict__ A,
                                          const float* __restrict__ Bw,
                                          float* __restrict__ C) {
    constexpr int BM = GBM, BN = GBN, BK = GBK, LDA = GLDA;
    constexpr int K = DMODEL, N = DMODEL;

    extern __shared__ float smg[];

    const int tid  = threadIdx.x;
    const int lane = tid & 31;
    const int warp = tid >> 5;
    const int wm = (warp >> 2) * 64;  // warp row offset in tile
    const int wn = (warp & 3) * 32;   // warp col offset in tile
    const int bm = blockIdx.y * BM;
    const int bn = blockIdx.x * BN;
    const int r0 = lane >> 2;         // 0..7
    const int cq = lane & 3;          // 0..3

    float acc[4][4][4];
#pragma unroll
    for (int i = 0; i < 4; i++)
#pragma unroll
        for (int j = 0; j < 4; j++)
#pragma unroll
            for (int t = 0; t < 4; t++) acc[i][j][t] = 0.f;

    // --- global loader for one staging slot (it = 0,1) ---
    auto load_g = [&](int kt, int it, float4& av, float4& bv) {
        int f   = tid + it * 256;      // 0..511
        int row = f >> 2;              // 0..127
        int c4  = (f & 3) * 4;         // 0..12
        if (AMODE == 0) {
            av = *(const float4*)(A + (size_t)(bm + row) * K + kt + c4);
        } else {
            int ig = bm + row;
            int b_ = ig >> 11, s = ig & 2047;
            int k0 = kt + c4;
            int h = k0 >> 6, d = k0 & 63;
            av = *(const float4*)(A + ((size_t)((b_ * HEADS + h) * SEQ + s)) * DK + d);
        }
        bv = *(const float4*)(Bw + (size_t)(bn + row) * K + kt + c4);
    };

    // --- convert prefetched regs and store into buffer p ---
    auto stage = [&](int p, float4 pa[2], float4 pb[2]) {
        float* As  = smg + p * GBUF;
        float* Bsh = As + GSLOT;
        float* Bsl = Bsh + GSLOT;
#pragma unroll
        for (int it = 0; it < 2; it++) {
            int f   = tid + it * 256;
            int row = f >> 2;
            int c4  = (f & 3) * 4;
            float4 av = pa[it], bv = pb[it];
            float4 at4, bh4, bl4;
            at4.x = __uint_as_float(f2tf(av.x)); at4.y = __uint_as_float(f2tf(av.y));
            at4.z = __uint_as_float(f2tf(av.z)); at4.w = __uint_as_float(f2tf(av.w));
            split_tf32(bv.x, bh4.x, bl4.x); split_tf32(bv.y, bh4.y, bl4.y);
            split_tf32(bv.z, bh4.z, bl4.z); split_tf32(bv.w, bh4.w, bl4.w);
            *(float4*)(As  + row * LDA + c4) = at4;
            *(float4*)(Bsh + row * LDA + c4) = bh4;
            *(float4*)(Bsl + row * LDA + c4) = bl4;
        }
    };

    float4 pa[2], pb[2];
#pragma unroll
    for (int it = 0; it < 2; it++) load_g(0, it, pa[it], pb[it]);
    stage(0, pa, pb);
    __syncthreads();

    int p = 0;
#pragma unroll 1
    for (int kt = 0; kt < K; kt += BK) {
        const bool more = (kt + BK < K);
        // ---- issue next tile's global loads (retire under MMA phase) ----
        if (more) {
#pragma unroll
            for (int it = 0; it < 2; it++) load_g(kt + BK, it, pa[it], pb[it]);
        }

        // ---- MMA phase on buffer p: 2 passes (a*bl, a*bh) ----
        const float* As  = smg + p * GBUF;
        const float* Bsh = As + GSLOT;
        const float* Bsl = Bsh + GSLOT;
#pragma unroll
        for (int ks = 0; ks < 2; ks++) {
            const int cb = ks * 8 + cq;
            unsigned fa[4][4], fb[4][2];

            // load A fragments (single tf32)
#pragma unroll
            for (int mi = 0; mi < 4; mi++) {
                int rb = wm + mi * 16 + r0;
                fa[mi][0] = __float_as_uint(As[rb * LDA + cb]);
                fa[mi][1] = __float_as_uint(As[(rb + 8) * LDA + cb]);
                fa[mi][2] = __float_as_uint(As[rb * LDA + cb + 4]);
                fa[mi][3] = __float_as_uint(As[(rb + 8) * LDA + cb + 4]);
            }
            // pass 1: A x B-lo
#pragma unroll
            for (int ni = 0; ni < 4; ni++) {
                int rb = wn + ni * 8 + r0;
                fb[ni][0] = __float_as_uint(Bsl[rb * LDA + cb]);
                fb[ni][1] = __float_as_uint(Bsl[rb * LDA + cb + 4]);
            }
#pragma unroll
            for (int mi = 0; mi < 4; mi++)
#pragma unroll
                for (int ni = 0; ni < 4; ni++)
                    mma8(acc[mi][ni], fa[mi][0], fa[mi][1], fa[mi][2], fa[mi][3],
                         fb[ni][0], fb[ni][1]);

            // pass 2: A x B-hi (reload fb; fa kept)
#pragma unroll
            for (int ni = 0; ni < 4; ni++) {
                int rb = wn + ni * 8 + r0;
                fb[ni][0] = __float_as_uint(Bsh[rb * LDA + cb]);
                fb[ni][1] = __float_as_uint(Bsh[rb * LDA + cb + 4]);
            }
#pragma unroll
            for (int mi = 0; mi < 4; mi++)
#pragma unroll
                for (int ni = 0; ni < 4; ni++)
                    mma8(acc[mi][ni], fa[mi][0], fa[mi][1], fa[mi][2], fa[mi][3],
                         fb[ni][0], fb[ni][1]);
        }

        // ---- stage next tile into the inactive buffer, then single barrier ----
        if (more) stage(p ^ 1, pa, pb);
        __syncthreads();
        p ^= 1;
    }

    // ---- epilogue ----
#pragma unroll
    for (int mi = 0; mi < 4; mi++) {
#pragma unroll
        for (int ni = 0; ni < 4; ni++) {
            int rg = bm + wm + mi * 16 + r0;
            int cg = bn + wn + ni * 8 + cq * 2;
            float2 p0 = make_float2(acc[mi][ni][0], acc[mi][ni][1]);
            float2 p1 = make_float2(acc[mi][ni][2], acc[mi][ni][3]);
            if (CMODE == 0) {
                *(float2*)(C + (size_t)rg * N + cg)       = p0;
                *(float2*)(C + (size_t)(rg + 8) * N + cg) = p1;
            } else {
                int b_ = rg >> 11, s = rg & 2047;
                int h = cg >> 6, d = cg & 63;
                float* dst = C + ((size_t)((b_ * HEADS + h) * SEQ + s)) * DK + d;
                *(float2*)dst            = p0;
                *(float2*)(dst + 8 * DK) = p1;
            }
        }
    }
}

__global__ void __launch_bounds__(256, 2)
proj_kernel(const float* __restrict__ q, const float* __restrict__ k,
            const float* __restrict__ v, const float* __restrict__ Wq,
            const float* __restrict__ Wk, const float* __restrict__ Wv) {
    int z = blockIdx.z;
    const float* A = (z == 0) ? q : (z == 1) ? k : v;
    const float* W = (z == 0) ? Wq : (z == 1) ? Wk : Wv;
    float* Cg = (z == 0) ? g_Qh : (z == 1) ? g_Kh : g_Vh;
    gemm_body<0, 1>(A, W, Cg);
}

__global__ void __launch_bounds__(256, 2)
out_kernel(const float* __restrict__ Wo, float* __restrict__ out) {
    gemm_body<1, 0>(g_Oh, Wo, out);
}

// ---------------------------------------------------------------------------
// Flash attention: block = 128 q-rows of one (b,h), 8 warps x 16 rows.
// Key tiles of 64. Q in registers (scaled by 1/8), 1xTF32 QK^T (R11),
// 1xTF32 PV. Online softmax in fp32.
// R3: next K/V tile prefetched into registers during the MMA+softmax phase.
// R5: K/V smem double-buffered -> single __syncthreads per key tile.
// ---------------------------------------------------------------------------
constexpr int ALK = 68, ALV = 72, ALP = 68;        // padded strides (floats)
constexpr int AKBUF = 64 * ALK + 64 * ALV;         // Ks+Vs per buffer (floats)
constexpr size_t ATT_SHM = (size_t)(2 * AKBUF + 128 * ALP) * sizeof(float) +
                           2 * 64 * sizeof(int);   // ~105 KB

__global__ void __launch_bounds__(256)
attn_kernel(const int* __restrict__ mask) {
    constexpr int BQ = 128, BKEY = 64;
    constexpr int LK = ALK, LV = ALV, LP = ALP;

    extern __shared__ float sm[];
    // [buf0: Ks|Vs][buf1: Ks|Vs][Ps][msk0|msk1]
    float* Ps  = sm + 2 * AKBUF;          // 128 x LP
    int*   msk = (int*)(Ps + 128 * LP);   // 2 x 64

    const int tid  = threadIdx.x;
    const int lane = tid & 31;
    const int warp = tid >> 5;
    const int r0 = lane >> 2;
    const int cq = lane & 3;
    const int wrow = warp * 16;

    const int bh = blockIdx.y;       // b*H + h
    const int b_ = bh >> 4;
    const int q0 = blockIdx.x * BQ;

    const float* Qg = g_Qh + (size_t)bh * SEQ * DK;
    const float* Kg = g_Kh + (size_t)bh * SEQ * DK;
    const float* Vg = g_Vh + (size_t)bh * SEQ * DK;
    float*       Og = g_Oh + (size_t)bh * SEQ * DK;
    const int*   mg = mask + b_ * SEQ;

    // Q fragments, 1/sqrt(dk) folded in.  qa[ks][{r0,c},{r0+8,c},{r0,c+4},{r0+8,c+4}]
    unsigned qa[8][4];
    {
        const float* qr  = Qg + (size_t)(q0 + wrow + r0) * DK;
        const float* qr8 = qr + 8 * DK;
#pragma unroll
        for (int ks = 0; ks < 8; ks++) {
            int c = ks * 8 + cq;
            qa[ks][0] = f2tf(qr[c] * 0.125f);
            qa[ks][1] = f2tf(qr8[c] * 0.125f);
            qa[ks][2] = f2tf(qr[c + 4] * 0.125f);
            qa[ks][3] = f2tf(qr8[c + 4] * 0.125f);
        }
    }

    // --- K/V tile prefetch state (4 slots of float4 each) ---
    const int pr_row = tid >> 4;          // 0..15 (+16 per slot)
    const int pr_c4  = (tid & 15) * 4;    // 0..60
    float4 pk[4], pv[4];
    int    pm;
    auto load_kv = [&](int kt) {
#pragma unroll
        for (int it = 0; it < 4; it++) {
            int row = pr_row + it * 16;
            pk[it] = *(const float4*)(Kg + (size_t)(kt + row) * DK + pr_c4);
            pv[it] = *(const float4*)(Vg + (size_t)(kt + row) * DK + pr_c4);
        }
        pm = (tid < 64) ? mg[kt + tid] : 0;
    };

    // --- convert prefetch regs into K/V buffer p (single tf32 round) ---
    auto stage_kv = [&](int p) {
        float* Ks = sm + p * AKBUF;
        float* Vs = Ks + 64 * LK;
#pragma unroll
        for (int it = 0; it < 4; it++) {
            int row = pr_row + it * 16;
            float4 kv = pk[it];
            float4 vv = pv[it];
            float4 kt4, vt;
            kt4.x = __uint_as_float(f2tf(kv.x)); kt4.y = __uint_as_float(f2tf(kv.y));
            kt4.z = __uint_as_float(f2tf(kv.z)); kt4.w = __uint_as_float(f2tf(kv.w));
            vt.x = __uint_as_float(f2tf(vv.x)); vt.y = __uint_as_float(f2tf(vv.y));
            vt.z = __uint_as_float(f2tf(vv.z)); vt.w = __uint_as_float(f2tf(vv.w));
            *(float4*)(Ks + row * LK + pr_c4) = kt4;
            *(float4*)(Vs + row * LV + pr_c4) = vt;
        }
        if (tid < 64) msk[p * 64 + tid] = pm;
    };

    load_kv(0);
    stage_kv(0);
    __syncthreads();

    float m0 = -1e30f, m1 = -1e30f, l0 = 0.f, l1 = 0.f;
    float o[8][4];
#pragma unroll
    for (int nf = 0; nf < 8; nf++)
#pragma unroll
        for (int t = 0; t < 4; t++) o[nf][t] = 0.f;

    int p = 0;
#pragma unroll 1
    for (int kt = 0; kt < SEQ; kt += BKEY) {
        const bool more = (kt + BKEY < SEQ);
        // ---- issue next tile's global loads (retire under MMA phase) ----
        if (more) load_kv(kt + BKEY);

        const float* Ks = sm + p * AKBUF;
        const float* Vs = Ks + 64 * LK;
        const int*   mk = msk + p * 64;

        // ---- S = Q K^T (1xTF32) ----
        float sacc[8][4];
#pragma unroll
        for (int nf = 0; nf < 8; nf++)
#pragma unroll
            for (int t = 0; t < 4; t++) sacc[nf][t] = 0.f;

#pragma unroll
        for (int ks = 0; ks < 8; ks++) {
#pragma unroll
            for (int nf = 0; nf < 8; nf++) {
                int rb = (nf * 8 + r0) * LK + ks * 8 + cq;
                unsigned k0v = __float_as_uint(Ks[rb]);
                unsigned k1v = __float_as_uint(Ks[rb + 4]);
                mma8(sacc[nf], qa[ks][0], qa[ks][1], qa[ks][2], qa[ks][3], k0v, k1v);
            }
        }

        // ---- mask + online softmax ----
        float mx0 = -1e30f, mx1 = -1e30f;
#pragma unroll
        for (int nf = 0; nf < 8; nf++) {
            int c = nf * 8 + cq * 2;
            if (mk[c] == 0)     { sacc[nf][0] = -1e9f; sacc[nf][2] = -1e9f; }
            if (mk[c + 1] == 0) { sacc[nf][1] = -1e9f; sacc[nf][3] = -1e9f; }
            mx0 = fmaxf(mx0, fmaxf(sacc[nf][0], sacc[nf][1]));
            mx1 = fmaxf(mx1, fmaxf(sacc[nf][2], sacc[nf][3]));
        }
        mx0 = fmaxf(mx0, __shfl_xor_sync(0xffffffffu, mx0, 1));
        mx0 = fmaxf(mx0, __shfl_xor_sync(0xffffffffu, mx0, 2));
        mx1 = fmaxf(mx1, __shfl_xor_sync(0xffffffffu, mx1, 1));
        mx1 = fmaxf(mx1, __shfl_xor_sync(0xffffffffu, mx1, 2));

        float mn0 = fmaxf(m0, mx0), mn1 = fmaxf(m1, mx1);
        float al0 = __expf(m0 - mn0), al1 = __expf(m1 - mn1);
        m0 = mn0; m1 = mn1;

        float rs0 = 0.f, rs1 = 0.f;
#pragma unroll
        for (int nf = 0; nf < 8; nf++) {
            sacc[nf][0] = __expf(sacc[nf][0] - m0);
            sacc[nf][1] = __expf(sacc[nf][1] - m0);
            sacc[nf][2] = __expf(sacc[nf][2] - m1);
            sacc[nf][3] = __expf(sacc[nf][3] - m1);
            rs0 += sacc[nf][0] + sacc[nf][1];
            rs1 += sacc[nf][2] + sacc[nf][3];
        }
        rs0 += __shfl_xor_sync(0xffffffffu, rs0, 1);
        rs0 += __shfl_xor_sync(0xffffffffu, rs0, 2);
        rs1 += __shfl_xor_sync(0xffffffffu, rs1, 1);
        rs1 += __shfl_xor_sync(0xffffffffu, rs1, 2);
        l0 = l0 * al0 + rs0;
        l1 = l1 * al1 + rs1;

#pragma unroll
        for (int nf = 0; nf < 8; nf++) {
            o[nf][0] *= al0; o[nf][1] *= al0;
            o[nf][2] *= al1; o[nf][3] *= al1;
        }

        // ---- write P (per-warp private rows; no cross-warp hazard) ----
#pragma unroll
        for (int nf = 0; nf < 8; nf++) {
            int c = nf * 8 + cq * 2;
            Ps[(wrow + r0) * LP + c]         = __uint_as_float(f2tf(sacc[nf][0]));
            Ps[(wrow + r0) * LP + c + 1]     = __uint_as_float(f2tf(sacc[nf][1]));
            Ps[(wrow + r0 + 8) * LP + c]     = __uint_as_float(f2tf(sacc[nf][2]));
            Ps[(wrow + r0 + 8) * LP + c + 1] = __uint_as_float(f2tf(sacc[nf][3]));
        }
        __syncwarp();

        // ---- O += P V ----
#pragma unroll
        for (int ks = 0; ks < 8; ks++) {
            int pc = ks * 8 + cq;
            unsigned pa0 = __float_as_uint(Ps[(wrow + r0) * LP + pc]);
            unsigned pa1 = __float_as_uint(Ps[(wrow + r0 + 8) * LP + pc]);
            unsigned pa2 = __float_as_uint(Ps[(wrow + r0) * LP + pc + 4]);
            unsigned pa3 = __float_as_uint(Ps[(wrow + r0 + 8) * LP + pc + 4]);
#pragma unroll
            for (int nf = 0; nf < 8; nf++) {
                int vb = (ks * 8 + cq) * LV + nf * 8 + r0;
                unsigned v0 = __float_as_uint(Vs[vb]);
                unsigned v1 = __float_as_uint(Vs[vb + 4 * LV]);
                mma8(o[nf], pa0, pa1, pa2, pa3, v0, v1);
            }
        }

        // ---- stage next tile into the inactive buffer, then single barrier ----
        if (more) stage_kv(p ^ 1);
        __syncthreads();
        p ^= 1;
    }

    // ---- epilogue: divide by l, store to g_Oh ----
    float i0 = 1.f / l0, i1 = 1.f / l1;
    int qr = q0 + wrow + r0;
#pragma unroll
    for (int nf = 0; nf < 8; nf++) {
        int d = nf * 8 + cq * 2;
        float2 p0 = make_float2(o[nf][0] * i0, o[nf][1] * i0);
        float2 p1 = make_float2(o[nf][2] * i1, o[nf][3] * i1);
        *(float2*)(Og + (size_t)qr * DK + d)       = p0;
        *(float2*)(Og + (size_t)(qr + 8) * DK + d) = p1;
    }
}

// ---------------------------------------------------------------------------
extern "C" void kernel_launch(void* const* d_in, const int* in_sizes, int n_in,
                              void* d_out, int out_size) {
    const float* q    = (const float*)d_in[0];
    const float* k    = (const float*)d_in[1];
    const float* v    = (const float*)d_in[2];
    const int*   mask = (const int*)d_in[3];
    const float* Wq   = (const float*)d_in[4];
    const float* Wk   = (const float*)d_in[5];
    const float* Wv   = (const float*)d_in[6];
    const float* Wo   = (const float*)d_in[7];
    float* out = (float*)d_out;

    dim3 blk(256);

    // GEMM kernels: 60 KB dynamic smem (double-buffered, 2xTF32), 2 CTAs/SM
    cudaFuncSetAttribute(proj_kernel, cudaFuncAttributeMaxDynamicSharedMemorySize,
                         (int)GEMM_SHM);
    cudaFuncSetAttribute(out_kernel, cudaFuncAttributeMaxDynamicSharedMemorySize,
                         (int)GEMM_SHM);

    // Q/K/V projections (z selects which)
    proj_kernel<<<dim3(DMODEL / 128, NTOK / 128, 3), blk, GEMM_SHM>>>(q, k, v, Wq, Wk, Wv);

    // Attention (double-buffered K/V, 1xTF32 QK^T: ~105 KB dynamic smem)
    cudaFuncSetAttribute(attn_kernel, cudaFuncAttributeMaxDynamicSharedMemorySize,
                         (int)ATT_SHM);
    attn_kernel<<<dim3(SEQ / 128, BATCH * HEADS), blk, ATT_SHM>>>(mask);

    // Output projection
    out_kernel<<<dim3(DMODEL / 128, NTOK / 128), blk, GEMM_SHM>>>(Wo, out);
}